// round 13
// baseline (speedup 1.0000x reference)
#include <cuda_runtime.h>
#include <math.h>
#include <stdint.h>

#define NDIM     128
#define TABK     256
#define BMAXF    8.0f
#define INV_BMAX 0.125f
#define ATT_SCALE 0.08838834764831845f  // 1/sqrt(128)
#define MAX_GRAPHS 16384
#define CAP      1024                    // smem attn cache per graph (nodes)

// -------- persistent device scratch (static allocation only) --------
__device__ float g_M[2][NDIM];               // Wq @ Wk^T
__device__ float g_Kb[2];                    // Wk @ bq
__device__ int   g_start[MAX_GRAPHS];        // per-graph node offsets
__device__ float g_psi[2][TABK + 1][NDIM];   // charge_embed table psi_j(beta)

__device__ __forceinline__ float silu_f(float z) {
    return z / (1.0f + expf(-z));
}
__device__ __forceinline__ float softplus_fast(float s) {
    return fmaxf(s, 0.0f) + __logf(1.0f + __expf(-fabsf(s)));
}

// ===== prep kernel: warp-cooperative 32-ary lower_bound + M,Kb ==============
#define PWARPS 8   // warps (graphs) per block

__global__ __launch_bounds__(256) void prep_kernel(
    const void* __restrict__ batch_raw, int ngraphs, int nnodes,
    const float* __restrict__ Wq, const float* __restrict__ bq,
    const float* __restrict__ Wk) {
    int bid = blockIdx.x;
    int tid = threadIdx.x;
    int nsb = (ngraphs + 1 + PWARPS - 1) / PWARPS;   // search blocks

    if (bid < nsb) {
        // ---- one warp per boundary g: 32-ary cooperative search ----
        int wid = tid >> 5, lane = tid & 31;
        int g = bid * PWARPS + wid;
        if (g > ngraphs) return;

        const int* b32 = (const int*)batch_raw;
        int w = (nnodes >= 8) ? ((nnodes & ~1) - 6) : 0;
        bool is64 = (b32[w + 1] == 0) && (b32[w + 3] == 0) && (b32[w + 5] == 0);
        const long long* b64 = (const long long*)batch_raw;
        long long gv = (long long)g;

        int lo = 0, hi = nnodes;     // invariant: b[lo-1] < g <= b[hi] (virtual)
        while (hi - lo > 32) {
            long long span = (long long)(hi - lo);
            int p = lo + (int)((span * (long long)(lane + 1)) >> 5);  // (lo, hi]
            bool lt = (p < hi) &&
                      ((is64 ? b64[p] : (long long)b32[p]) < gv);
            unsigned m = __ballot_sync(0xffffffffu, lt);
            int c = __popc(m);       // lt lanes form a prefix (sorted array)
            int pc1 = __shfl_sync(0xffffffffu, p, (c > 0) ? (c - 1) : 0);
            int pc  = __shfl_sync(0xffffffffu, p, (c < 32) ? c : 31);
            if (c > 0)  lo = pc1 + 1;
            if (c < 32) hi = pc;
        }
        // tail: span <= 32, one parallel probe round
        {
            int p = lo + lane;
            bool ge = (p >= hi) ||
                      ((is64 ? b64[p] : (long long)b32[p]) >= gv);
            unsigned m = __ballot_sync(0xffffffffu, ge);
            int res = (m == 0u) ? hi : (lo + (__ffs(m) - 1));
            if (lane == 0) g_start[g] = res;
        }
    } else {
        // ---- M, Kb role ----
        int j = tid >> 7, e = tid & 127;
        const float* wk = Wk + j * NDIM;
        float m = 0.f;
        #pragma unroll 8
        for (int d = 0; d < NDIM; d++) m = fmaf(Wq[e * NDIM + d], wk[d], m);
        g_M[j][e] = m;
        if (tid < 2) {
            float kb = 0.f;
            for (int d = 0; d < NDIM; d++) kb = fmaf(Wk[tid * NDIM + d], bq[d], kb);
            g_Kb[tid] = kb;
        }
    }
}

// ========= table kernel: one beta point per block; PDL trigger at start =====
#define NTPTS (TABK + 1)       // 257
#define NTAB2 (2 * NTPTS)      // 514

__global__ __launch_bounds__(128) void table_kernel(
    const float* __restrict__ Wv, const float* __restrict__ W1,
    const float* __restrict__ b1, const float* __restrict__ W2,
    const float* __restrict__ b2) {
    cudaTriggerProgrammaticLaunchCompletion();   // let main start phase A now

    int bid = blockIdx.x;
    int tid = threadIdx.x;
    int j = bid / NTPTS;
    int t = bid - j * NTPTS;
    int n = tid;
    float x = (float)t / (float)TABK;
    float beta = BMAXF * x * x;

    float ua = 0.f, ub = 0.f, uc = 0.f, ud = 0.f;
    #pragma unroll 4
    for (int ee = 0; ee < NDIM; ee += 4) {
        ua = fmaf(Wv[j * NDIM + ee + 0], W1[(ee + 0) * NDIM + n], ua);
        ub = fmaf(Wv[j * NDIM + ee + 1], W1[(ee + 1) * NDIM + n], ub);
        uc = fmaf(Wv[j * NDIM + ee + 2], W1[(ee + 2) * NDIM + n], uc);
        ud = fmaf(Wv[j * NDIM + ee + 3], W1[(ee + 3) * NDIM + n], ud);
    }
    float u2 = (ua + ub) + (uc + ud);

    __shared__ float h1s[NDIM];
    h1s[n] = silu_f(fmaf(beta, u2, b1[n]));
    __syncthreads();

    float ya = 0.f, yb = 0.f, yc = 0.f, yd = 0.f;
    #pragma unroll 4
    for (int d = 0; d < NDIM; d += 4) {
        ya = fmaf(h1s[d + 0], W2[(d + 0) * NDIM + n], ya);
        yb = fmaf(h1s[d + 1], W2[(d + 1) * NDIM + n], yb);
        yc = fmaf(h1s[d + 2], W2[(d + 2) * NDIM + n], yc);
        yd = fmaf(h1s[d + 3], W2[(d + 3) * NDIM + n], yd);
    }
    float y = (ya + yb) + (yc + yd);
    g_psi[j][t][n] = fmaf(beta, Wv[j * NDIM + n], silu_f(y + b2[n]));
}

// ===== main: R6 structure; grid-sync BETWEEN phase A and phase B =====
#define NW  4
#define NPB (NW * 8)   // phase A: 8 nodes per warp per iteration
#define NPB_B (NW * 4) // phase B: 4 nodes per warp per iteration

__global__ __launch_bounds__(128, 8) void main_kernel(
    const float* __restrict__ ns, const float* __restrict__ charge,
    float* __restrict__ out, int ngraphs) {
    int tid  = threadIdx.x;
    int wid  = tid >> 5, lane = tid & 31;
    int l8   = lane & 7;
    int grp  = lane >> 3;
    __shared__ float warpsum[NW];
    __shared__ float sm_attn[CAP];

    int g = blockIdx.x;
    if (g >= ngraphs) { cudaGridDependencySynchronize(); return; }

    // prep outputs are safe pre-sync: prep completed before table started,
    // and main cannot start before table starts (stream order + PDL).
    float q  = charge[g];
    float r0 = fmaxf(q, 0.f), r1 = fmaxf(-q, 0.f);
    float c0 = fminf(r0, 1.f), c1 = fminf(r1, 1.f);
    float cg = c0 * g_Kb[0] + c1 * g_Kb[1];
    int   jj = (q < 0.f) ? 1 : 0;
    float qb = fmaxf(r0, r1);
    int n0 = g_start[g], n1 = g_start[g + 1];

    // combined projection Mc = c0*M0 + c1*M1, this lane's 16-float slice
    float4 Mc[4];
    #pragma unroll
    for (int jc = 0; jc < 4; jc++) {
        int e = jc * 32 + l8 * 4;
        float4 a = *reinterpret_cast<const float4*>(&g_M[0][e]);
        float4 b = *reinterpret_cast<const float4*>(&g_M[1][e]);
        Mc[jc].x = c0 * a.x + c1 * b.x;
        Mc[jc].y = c0 * a.y + c1 * b.y;
        Mc[jc].z = c0 * a.z + c1 * b.z;
        Mc[jc].w = c0 * a.w + c1 * b.w;
    }

    // ---- phase A: 2 nodes per 8-lane group per iter; loads front-batched ----
    float acc = 0.f;
    for (int base = n0; base < n1; base += NPB) {
        int nd0 = base + wid * 8 + grp * 2;
        int nd1 = nd0 + 1;
        bool v0 = nd0 < n1, v1 = nd1 < n1;
        float4 va[4], vb[4];
        const float* ra = ns + (long)nd0 * NDIM + l8 * 4;
        const float* rb = ns + (long)nd1 * NDIM + l8 * 4;
        #pragma unroll
        for (int jc = 0; jc < 4; jc++)
            va[jc] = v0 ? *reinterpret_cast<const float4*>(ra + jc * 32)
                        : make_float4(0.f, 0.f, 0.f, 0.f);
        #pragma unroll
        for (int jc = 0; jc < 4; jc++)
            vb[jc] = v1 ? *reinterpret_cast<const float4*>(rb + jc * 32)
                        : make_float4(0.f, 0.f, 0.f, 0.f);
        float s0 = 0.f, s1 = 0.f;
        #pragma unroll
        for (int jc = 0; jc < 4; jc++) {
            s0 += va[jc].x * Mc[jc].x + va[jc].y * Mc[jc].y
                + va[jc].z * Mc[jc].z + va[jc].w * Mc[jc].w;
            s1 += vb[jc].x * Mc[jc].x + vb[jc].y * Mc[jc].y
                + vb[jc].z * Mc[jc].z + vb[jc].w * Mc[jc].w;
        }
        s0 += __shfl_xor_sync(0xffffffffu, s0, 1);
        s1 += __shfl_xor_sync(0xffffffffu, s1, 1);
        s0 += __shfl_xor_sync(0xffffffffu, s0, 2);
        s1 += __shfl_xor_sync(0xffffffffu, s1, 2);
        s0 += __shfl_xor_sync(0xffffffffu, s0, 4);
        s1 += __shfl_xor_sync(0xffffffffu, s1, 4);
        if (l8 == 0) {
            if (v0) {
                float a0 = softplus_fast((s0 + cg) * ATT_SCALE);
                acc += a0;
                int li = nd0 - n0;
                if (li < CAP) sm_attn[li] = a0;
            }
            if (v1) {
                float a1 = softplus_fast((s1 + cg) * ATT_SCALE);
                acc += a1;
                int li = nd1 - n0;
                if (li < CAP) sm_attn[li] = a1;
            }
        }
    }
    #pragma unroll
    for (int o = 16; o > 0; o >>= 1) acc += __shfl_xor_sync(0xffffffffu, acc, o);
    if (lane == 0) warpsum[wid] = acc;
    __syncthreads();
    float asum = warpsum[0] + warpsum[1] + warpsum[2] + warpsum[3];
    float inv = 1.0f / asum;

    // ---- wait for table grid (psi needed only from here) ----
    cudaGridDependencySynchronize();

    // ---- phase B: table epilogue; evict-first reads, streaming stores ----
    for (int base = n0; base < n1; base += NPB_B) {
        int node = base + wid * 4 + grp;
        if (node >= n1) continue;
        int li = node - n0;
        float attn;
        if (li < CAP) {
            attn = sm_attn[li];
        } else {
            float s = 0.f;
            const float* row = ns + (long)node * NDIM + l8 * 4;
            #pragma unroll
            for (int jc = 0; jc < 4; jc++) {
                float4 v = __ldcs(reinterpret_cast<const float4*>(row + jc * 32));
                s += v.x * Mc[jc].x + v.y * Mc[jc].y + v.z * Mc[jc].z + v.w * Mc[jc].w;
            }
            s += __shfl_xor_sync(0xffffffffu, s, 1);
            s += __shfl_xor_sync(0xffffffffu, s, 2);
            s += __shfl_xor_sync(0xffffffffu, s, 4);
            attn = softplus_fast((s + cg) * ATT_SCALE);
        }
        float beta = attn * inv * qb;
        float tf = (float)TABK * sqrtf(beta * INV_BMAX);
        int idx = (int)tf;
        if (idx > TABK - 1) idx = TABK - 1;
        float f = tf - (float)idx;
        const float* pa = &g_psi[jj][idx][0];
        const float* row = ns + (long)node * NDIM;
        float* orow = out + (long)node * NDIM;
        #pragma unroll
        for (int jc = 0; jc < 4; jc++) {
            int e = jc * 32 + l8 * 4;
            float4 v = __ldcs(reinterpret_cast<const float4*>(row + e));
            float4 a = *reinterpret_cast<const float4*>(pa + e);
            float4 b = *reinterpret_cast<const float4*>(pa + NDIM + e);
            float4 o4;
            o4.x = v.x + fmaf(f, b.x - a.x, a.x);
            o4.y = v.y + fmaf(f, b.y - a.y, a.y);
            o4.z = v.z + fmaf(f, b.z - a.z, a.z);
            o4.w = v.w + fmaf(f, b.w - a.w, a.w);
            __stcs(reinterpret_cast<float4*>(orow + e), o4);
        }
    }
}

extern "C" void kernel_launch(void* const* d_in, const int* in_sizes, int n_in,
                              void* d_out, int out_size) {
    const float* ns     = (const float*)d_in[0];
    const float* charge = (const float*)d_in[1];
    const void*  batch  = (const void*) d_in[2];
    const float* Wq     = (const float*)d_in[3];
    const float* bq     = (const float*)d_in[4];
    const float* Wk     = (const float*)d_in[5];
    const float* Wv     = (const float*)d_in[6];
    const float* W1     = (const float*)d_in[7];
    const float* b1     = (const float*)d_in[8];
    const float* W2     = (const float*)d_in[9];
    const float* b2     = (const float*)d_in[10];
    float* out = (float*)d_out;

    int nnodes  = in_sizes[0] / NDIM;
    int ngraphs = in_sizes[1];

    // 1) prep: warp-cooperative boundary search + M,Kb (short, wide)
    int nsb = (ngraphs + 1 + PWARPS - 1) / PWARPS;
    prep_kernel<<<nsb + 1, 256>>>(batch, ngraphs, nnodes, Wq, bq, Wk);

    // 2) table: PDL primary, triggers at block start
    table_kernel<<<NTAB2, 128>>>(Wv, W1, b1, W2, b2);

    // 3) main: PDL secondary; phase A overlaps table build, syncs before B
    cudaLaunchConfig_t cfg = {};
    cfg.gridDim  = dim3((unsigned)ngraphs, 1, 1);
    cfg.blockDim = dim3(128, 1, 1);
    cfg.dynamicSmemBytes = 0;
    cfg.stream = 0;
    cudaLaunchAttribute attrs[1];
    attrs[0].id = cudaLaunchAttributeProgrammaticStreamSerialization;
    attrs[0].val.programmaticStreamSerializationAllowed = 1;
    cfg.attrs = attrs;
    cfg.numAttrs = 1;
    cudaLaunchKernelEx(&cfg, main_kernel, ns, charge, out, ngraphs);
}

// round 14
// speedup vs baseline: 1.0482x; 1.0482x over previous
#include <cuda_runtime.h>
#include <math.h>
#include <stdint.h>

#define NDIM     128
#define TABK     256
#define BMAXF    8.0f
#define INV_BMAX 0.125f
#define ATT_SCALE 0.08838834764831845f  // 1/sqrt(128)
#define MAX_GRAPHS 16384
#define CAP      1024                    // smem attn cache per graph (nodes)

// -------- persistent device scratch (static allocation only) --------
__device__ float g_M[2][NDIM];               // Wq @ Wk^T
__device__ float g_Kb[2];                    // Wk @ bq
__device__ int   g_start[MAX_GRAPHS];        // per-graph node offsets
__device__ float g_psi[2][TABK + 1][NDIM];   // charge_embed table psi_j(beta)

__device__ __forceinline__ float silu_f(float z) {
    return z / (1.0f + expf(-z));
}
__device__ __forceinline__ float softplus_fast(float s) {
    return fmaxf(s, 0.0f) + __logf(1.0f + __expf(-fabsf(s)));
}

// ===== fused aux kernel ======================================================
// Grid layout (blockDim 256):
//   [0, NSB)         starts role: 8 warps x 32-ary coop search; fence; trigger
//   NSB              M/Kb role: write g_M, g_Kb; fence; trigger
//   [NSB+1, +NTAB2)  table role: trigger FIRST, then build psi
// Main (PDL secondary) launches only after ALL blocks trigger => all
// g_start/g_M/g_Kb writes are complete and L2-visible before main starts.
#define PWARPS 8
#define NTPTS (TABK + 1)       // 257
#define NTAB2 (2 * NTPTS)      // 514

__global__ __launch_bounds__(256) void aux_kernel(
    const void* __restrict__ batch_raw, int ngraphs, int nnodes, int nsb,
    const float* __restrict__ Wq, const float* __restrict__ bq,
    const float* __restrict__ Wk, const float* __restrict__ Wv,
    const float* __restrict__ W1, const float* __restrict__ b1,
    const float* __restrict__ W2, const float* __restrict__ b2) {
    int bid = blockIdx.x;
    int tid = threadIdx.x;

    if (bid < nsb) {
        // ---- starts role: one warp per boundary g ----
        int wid = tid >> 5, lane = tid & 31;
        int g = bid * PWARPS + wid;
        if (g <= ngraphs) {
            const int* b32 = (const int*)batch_raw;
            int w = (nnodes >= 8) ? ((nnodes & ~1) - 6) : 0;
            bool is64 = (b32[w + 1] == 0) && (b32[w + 3] == 0) && (b32[w + 5] == 0);
            const long long* b64 = (const long long*)batch_raw;
            long long gv = (long long)g;
            int lo = 0, hi = nnodes;
            while (hi - lo > 32) {
                long long span = (long long)(hi - lo);
                int p = lo + (int)((span * (long long)(lane + 1)) >> 5);
                bool lt = (p < hi) && ((is64 ? b64[p] : (long long)b32[p]) < gv);
                unsigned m = __ballot_sync(0xffffffffu, lt);
                int c = __popc(m);
                int pc1 = __shfl_sync(0xffffffffu, p, (c > 0) ? (c - 1) : 0);
                int pc  = __shfl_sync(0xffffffffu, p, (c < 32) ? c : 31);
                if (c > 0)  lo = pc1 + 1;
                if (c < 32) hi = pc;
            }
            int p = lo + lane;
            bool ge = (p >= hi) || ((is64 ? b64[p] : (long long)b32[p]) >= gv);
            unsigned m = __ballot_sync(0xffffffffu, ge);
            int res = (m == 0u) ? hi : (lo + (__ffs(m) - 1));
            if (lane == 0) g_start[g] = res;
        }
        __threadfence();
        cudaTriggerProgrammaticLaunchCompletion();
    } else if (bid == nsb) {
        // ---- M, Kb role ----
        int j = tid >> 7, e = tid & 127;
        const float* wk = Wk + j * NDIM;
        float m = 0.f;
        #pragma unroll 8
        for (int d = 0; d < NDIM; d++) m = fmaf(Wq[e * NDIM + d], wk[d], m);
        g_M[j][e] = m;
        if (tid < 2) {
            float kb = 0.f;
            for (int d = 0; d < NDIM; d++) kb = fmaf(Wk[tid * NDIM + d], bq[d], kb);
            g_Kb[tid] = kb;
        }
        __threadfence();
        cudaTriggerProgrammaticLaunchCompletion();
    } else {
        // ---- table role: trigger first, then build psi ----
        cudaTriggerProgrammaticLaunchCompletion();
        if (tid >= 128) return;
        int tb = bid - (nsb + 1);
        int j = tb / NTPTS;
        int t = tb - j * NTPTS;
        int n = tid;
        float x = (float)t / (float)TABK;
        float beta = BMAXF * x * x;

        float ua = 0.f, ub = 0.f, uc = 0.f, ud = 0.f;
        #pragma unroll 4
        for (int ee = 0; ee < NDIM; ee += 4) {
            ua = fmaf(Wv[j * NDIM + ee + 0], W1[(ee + 0) * NDIM + n], ua);
            ub = fmaf(Wv[j * NDIM + ee + 1], W1[(ee + 1) * NDIM + n], ub);
            uc = fmaf(Wv[j * NDIM + ee + 2], W1[(ee + 2) * NDIM + n], uc);
            ud = fmaf(Wv[j * NDIM + ee + 3], W1[(ee + 3) * NDIM + n], ud);
        }
        float u2 = (ua + ub) + (uc + ud);

        __shared__ float h1s[NDIM];
        h1s[n] = silu_f(fmaf(beta, u2, b1[n]));
        __syncthreads();

        float ya = 0.f, yb = 0.f, yc = 0.f, yd = 0.f;
        #pragma unroll 4
        for (int d = 0; d < NDIM; d += 4) {
            ya = fmaf(h1s[d + 0], W2[(d + 0) * NDIM + n], ya);
            yb = fmaf(h1s[d + 1], W2[(d + 1) * NDIM + n], yb);
            yc = fmaf(h1s[d + 2], W2[(d + 2) * NDIM + n], yc);
            yd = fmaf(h1s[d + 3], W2[(d + 3) * NDIM + n], yd);
        }
        float y = (ya + yb) + (yc + yd);
        g_psi[j][t][n] = fmaf(beta, Wv[j * NDIM + n], silu_f(y + b2[n]));
    }
}

// ===== main: R12 structure (unchanged); grid-sync BETWEEN phase A and B =====
#define NW  4
#define NPB (NW * 8)   // phase A: 8 nodes per warp per iteration
#define NPB_B (NW * 4) // phase B: 4 nodes per warp per iteration

__global__ __launch_bounds__(128, 8) void main_kernel(
    const float* __restrict__ ns, const float* __restrict__ charge,
    float* __restrict__ out, int ngraphs) {
    int tid  = threadIdx.x;
    int wid  = tid >> 5, lane = tid & 31;
    int l8   = lane & 7;
    int grp  = lane >> 3;
    __shared__ float warpsum[NW];
    __shared__ float sm_attn[CAP];

    int g = blockIdx.x;
    if (g >= ngraphs) { cudaGridDependencySynchronize(); return; }

    // g_start/g_M/g_Kb written + fenced before every aux block triggered,
    // and main's L1 is fresh at launch => safe to read pre-sync.
    float q  = charge[g];
    float r0 = fmaxf(q, 0.f), r1 = fmaxf(-q, 0.f);
    float c0 = fminf(r0, 1.f), c1 = fminf(r1, 1.f);
    float cg = c0 * g_Kb[0] + c1 * g_Kb[1];
    int   jj = (q < 0.f) ? 1 : 0;
    float qb = fmaxf(r0, r1);
    int n0 = g_start[g], n1 = g_start[g + 1];

    // combined projection Mc = c0*M0 + c1*M1, this lane's 16-float slice
    float4 Mc[4];
    #pragma unroll
    for (int jc = 0; jc < 4; jc++) {
        int e = jc * 32 + l8 * 4;
        float4 a = *reinterpret_cast<const float4*>(&g_M[0][e]);
        float4 b = *reinterpret_cast<const float4*>(&g_M[1][e]);
        Mc[jc].x = c0 * a.x + c1 * b.x;
        Mc[jc].y = c0 * a.y + c1 * b.y;
        Mc[jc].z = c0 * a.z + c1 * b.z;
        Mc[jc].w = c0 * a.w + c1 * b.w;
    }

    // ---- phase A: 2 nodes per 8-lane group per iter; loads front-batched ----
    float acc = 0.f;
    for (int base = n0; base < n1; base += NPB) {
        int nd0 = base + wid * 8 + grp * 2;
        int nd1 = nd0 + 1;
        bool v0 = nd0 < n1, v1 = nd1 < n1;
        float4 va[4], vb[4];
        const float* ra = ns + (long)nd0 * NDIM + l8 * 4;
        const float* rb = ns + (long)nd1 * NDIM + l8 * 4;
        #pragma unroll
        for (int jc = 0; jc < 4; jc++)
            va[jc] = v0 ? *reinterpret_cast<const float4*>(ra + jc * 32)
                        : make_float4(0.f, 0.f, 0.f, 0.f);
        #pragma unroll
        for (int jc = 0; jc < 4; jc++)
            vb[jc] = v1 ? *reinterpret_cast<const float4*>(rb + jc * 32)
                        : make_float4(0.f, 0.f, 0.f, 0.f);
        float s0 = 0.f, s1 = 0.f;
        #pragma unroll
        for (int jc = 0; jc < 4; jc++) {
            s0 += va[jc].x * Mc[jc].x + va[jc].y * Mc[jc].y
                + va[jc].z * Mc[jc].z + va[jc].w * Mc[jc].w;
            s1 += vb[jc].x * Mc[jc].x + vb[jc].y * Mc[jc].y
                + vb[jc].z * Mc[jc].z + vb[jc].w * Mc[jc].w;
        }
        s0 += __shfl_xor_sync(0xffffffffu, s0, 1);
        s1 += __shfl_xor_sync(0xffffffffu, s1, 1);
        s0 += __shfl_xor_sync(0xffffffffu, s0, 2);
        s1 += __shfl_xor_sync(0xffffffffu, s1, 2);
        s0 += __shfl_xor_sync(0xffffffffu, s0, 4);
        s1 += __shfl_xor_sync(0xffffffffu, s1, 4);
        if (l8 == 0) {
            if (v0) {
                float a0 = softplus_fast((s0 + cg) * ATT_SCALE);
                acc += a0;
                int li = nd0 - n0;
                if (li < CAP) sm_attn[li] = a0;
            }
            if (v1) {
                float a1 = softplus_fast((s1 + cg) * ATT_SCALE);
                acc += a1;
                int li = nd1 - n0;
                if (li < CAP) sm_attn[li] = a1;
            }
        }
    }
    #pragma unroll
    for (int o = 16; o > 0; o >>= 1) acc += __shfl_xor_sync(0xffffffffu, acc, o);
    if (lane == 0) warpsum[wid] = acc;
    __syncthreads();
    float asum = warpsum[0] + warpsum[1] + warpsum[2] + warpsum[3];
    float inv = 1.0f / asum;

    // ---- wait for aux grid completion (psi needed only from here) ----
    cudaGridDependencySynchronize();

    // ---- phase B: table epilogue; evict-first reads, streaming stores ----
    for (int base = n0; base < n1; base += NPB_B) {
        int node = base + wid * 4 + grp;
        if (node >= n1) continue;
        int li = node - n0;
        float attn;
        if (li < CAP) {
            attn = sm_attn[li];
        } else {
            float s = 0.f;
            const float* row = ns + (long)node * NDIM + l8 * 4;
            #pragma unroll
            for (int jc = 0; jc < 4; jc++) {
                float4 v = __ldcs(reinterpret_cast<const float4*>(row + jc * 32));
                s += v.x * Mc[jc].x + v.y * Mc[jc].y + v.z * Mc[jc].z + v.w * Mc[jc].w;
            }
            s += __shfl_xor_sync(0xffffffffu, s, 1);
            s += __shfl_xor_sync(0xffffffffu, s, 2);
            s += __shfl_xor_sync(0xffffffffu, s, 4);
            attn = softplus_fast((s + cg) * ATT_SCALE);
        }
        float beta = attn * inv * qb;
        float tf = (float)TABK * sqrtf(beta * INV_BMAX);
        int idx = (int)tf;
        if (idx > TABK - 1) idx = TABK - 1;
        float f = tf - (float)idx;
        const float* pa = &g_psi[jj][idx][0];
        const float* row = ns + (long)node * NDIM;
        float* orow = out + (long)node * NDIM;
        #pragma unroll
        for (int jc = 0; jc < 4; jc++) {
            int e = jc * 32 + l8 * 4;
            float4 v = __ldcs(reinterpret_cast<const float4*>(row + e));
            float4 a = *reinterpret_cast<const float4*>(pa + e);
            float4 b = *reinterpret_cast<const float4*>(pa + NDIM + e);
            float4 o4;
            o4.x = v.x + fmaf(f, b.x - a.x, a.x);
            o4.y = v.y + fmaf(f, b.y - a.y, a.y);
            o4.z = v.z + fmaf(f, b.z - a.z, a.z);
            o4.w = v.w + fmaf(f, b.w - a.w, a.w);
            __stcs(reinterpret_cast<float4*>(orow + e), o4);
        }
    }
}

extern "C" void kernel_launch(void* const* d_in, const int* in_sizes, int n_in,
                              void* d_out, int out_size) {
    const float* ns     = (const float*)d_in[0];
    const float* charge = (const float*)d_in[1];
    const void*  batch  = (const void*) d_in[2];
    const float* Wq     = (const float*)d_in[3];
    const float* bq     = (const float*)d_in[4];
    const float* Wk     = (const float*)d_in[5];
    const float* Wv     = (const float*)d_in[6];
    const float* W1     = (const float*)d_in[7];
    const float* b1     = (const float*)d_in[8];
    const float* W2     = (const float*)d_in[9];
    const float* b2     = (const float*)d_in[10];
    float* out = (float*)d_out;

    int nnodes  = in_sizes[0] / NDIM;
    int ngraphs = in_sizes[1];

    // fused aux: starts + M/Kb (pre-trigger) and table (post-trigger)
    int nsb = (ngraphs + 1 + PWARPS - 1) / PWARPS;
    aux_kernel<<<nsb + 1 + NTAB2, 256>>>(batch, ngraphs, nnodes, nsb,
                                         Wq, bq, Wk, Wv, W1, b1, W2, b2);

    // main: PDL secondary — launches once all aux blocks triggered
    cudaLaunchConfig_t cfg = {};
    cfg.gridDim  = dim3((unsigned)ngraphs, 1, 1);
    cfg.blockDim = dim3(128, 1, 1);
    cfg.dynamicSmemBytes = 0;
    cfg.stream = 0;
    cudaLaunchAttribute attrs[1];
    attrs[0].id = cudaLaunchAttributeProgrammaticStreamSerialization;
    attrs[0].val.programmaticStreamSerializationAllowed = 1;
    cfg.attrs = attrs;
    cfg.numAttrs = 1;
    cudaLaunchKernelEx(&cfg, main_kernel, ns, charge, out, ngraphs);
}

// round 15
// speedup vs baseline: 1.0769x; 1.0274x over previous
#include <cuda_runtime.h>
#include <math.h>
#include <stdint.h>

#define NDIM     128
#define TABK     256
#define BMAXF    8.0f
#define INV_BMAX 0.125f
#define ATT_SCALE 0.08838834764831845f  // 1/sqrt(128)
#define CAP      1024                    // smem attn cache per graph (nodes)

// -------- persistent device scratch (static allocation only) --------
__device__ float g_M[2][NDIM];               // Wq @ Wk^T
__device__ float g_Kb[2];                    // Wk @ bq
__device__ float g_psi[2][TABK + 1][NDIM];   // charge_embed table psi_j(beta)

__device__ __forceinline__ float silu_f(float z) {
    return z / (1.0f + expf(-z));
}
__device__ __forceinline__ float softplus_fast(float s) {
    return fmaxf(s, 0.0f) + __logf(1.0f + __expf(-fabsf(s)));
}

// ===== aux kernel: block 0 = M/Kb (pre-trigger), rest = psi table ===========
#define NTPTS (TABK + 1)       // 257
#define NTAB2 (2 * NTPTS)      // 514

__global__ __launch_bounds__(128) void aux_kernel(
    const float* __restrict__ Wq, const float* __restrict__ bq,
    const float* __restrict__ Wk, const float* __restrict__ Wv,
    const float* __restrict__ W1, const float* __restrict__ b1,
    const float* __restrict__ W2, const float* __restrict__ b2) {
    int bid = blockIdx.x;
    int tid = threadIdx.x;

    if (bid == 0) {
        // ---- M, Kb role: publish BEFORE trigger ----
        int e = tid;
        float m0 = 0.f, m1 = 0.f;
        #pragma unroll 8
        for (int d = 0; d < NDIM; d++) {
            float wq = Wq[e * NDIM + d];
            m0 = fmaf(wq, Wk[d], m0);
            m1 = fmaf(wq, Wk[NDIM + d], m1);
        }
        g_M[0][e] = m0;
        g_M[1][e] = m1;
        if (tid < 2) {
            float kb = 0.f;
            for (int d = 0; d < NDIM; d++) kb = fmaf(Wk[tid * NDIM + d], bq[d], kb);
            g_Kb[tid] = kb;
        }
        __threadfence();
        cudaTriggerProgrammaticLaunchCompletion();
    } else {
        // ---- table role: trigger first, then build psi ----
        cudaTriggerProgrammaticLaunchCompletion();
        int tb = bid - 1;
        int j = tb / NTPTS;
        int t = tb - j * NTPTS;
        int n = tid;
        float x = (float)t / (float)TABK;
        float beta = BMAXF * x * x;

        float ua = 0.f, ub = 0.f, uc = 0.f, ud = 0.f;
        #pragma unroll 4
        for (int ee = 0; ee < NDIM; ee += 4) {
            ua = fmaf(Wv[j * NDIM + ee + 0], W1[(ee + 0) * NDIM + n], ua);
            ub = fmaf(Wv[j * NDIM + ee + 1], W1[(ee + 1) * NDIM + n], ub);
            uc = fmaf(Wv[j * NDIM + ee + 2], W1[(ee + 2) * NDIM + n], uc);
            ud = fmaf(Wv[j * NDIM + ee + 3], W1[(ee + 3) * NDIM + n], ud);
        }
        float u2 = (ua + ub) + (uc + ud);

        __shared__ float h1s[NDIM];
        h1s[n] = silu_f(fmaf(beta, u2, b1[n]));
        __syncthreads();

        float ya = 0.f, yb = 0.f, yc = 0.f, yd = 0.f;
        #pragma unroll 4
        for (int d = 0; d < NDIM; d += 4) {
            ya = fmaf(h1s[d + 0], W2[(d + 0) * NDIM + n], ya);
            yb = fmaf(h1s[d + 1], W2[(d + 1) * NDIM + n], yb);
            yc = fmaf(h1s[d + 2], W2[(d + 2) * NDIM + n], yc);
            yd = fmaf(h1s[d + 3], W2[(d + 3) * NDIM + n], yd);
        }
        float y = (ya + yb) + (yc + yd);
        g_psi[j][t][n] = fmaf(beta, Wv[j * NDIM + n], silu_f(y + b2[n]));
    }
}

// ===== main: pre-sync own-bounds coop search; grid-sync before phase B =====
#define NW  4
#define NPB (NW * 8)   // phase A: 8 nodes per warp per iteration
#define NPB_B (NW * 4) // phase B: 4 nodes per warp per iteration

__global__ __launch_bounds__(128, 8) void main_kernel(
    const float* __restrict__ ns, const float* __restrict__ charge,
    const void* __restrict__ batch_raw, int nnodes, int ngraphs,
    float* __restrict__ out) {
    int tid  = threadIdx.x;
    int wid  = tid >> 5, lane = tid & 31;
    int l8   = lane & 7;
    int grp  = lane >> 3;
    __shared__ float warpsum[NW];
    __shared__ float sm_attn[CAP];
    __shared__ int bounds[2];

    int g = blockIdx.x;
    if (g >= ngraphs) { cudaGridDependencySynchronize(); return; }

    // ---------- PRE-SYNC: g_M/g_Kb are pre-trigger-published by aux ----------
    float q  = charge[g];
    float r0 = fmaxf(q, 0.f), r1 = fmaxf(-q, 0.f);
    float c0 = fminf(r0, 1.f), c1 = fminf(r1, 1.f);
    float cg = c0 * g_Kb[0] + c1 * g_Kb[1];
    int   jj = (q < 0.f) ? 1 : 0;
    float qb = fmaxf(r0, r1);

    // combined projection Mc = c0*M0 + c1*M1, this lane's 16-float slice
    float4 Mc[4];
    #pragma unroll
    for (int jc = 0; jc < 4; jc++) {
        int e = jc * 32 + l8 * 4;
        float4 a = *reinterpret_cast<const float4*>(&g_M[0][e]);
        float4 b = *reinterpret_cast<const float4*>(&g_M[1][e]);
        Mc[jc].x = c0 * a.x + c1 * b.x;
        Mc[jc].y = c0 * a.y + c1 * b.y;
        Mc[jc].z = c0 * a.z + c1 * b.z;
        Mc[jc].w = c0 * a.w + c1 * b.w;
    }

    // warps 0/1: warp-cooperative 32-ary lower_bound for boundaries g, g+1
    if (wid < 2) {
        const int* b32 = (const int*)batch_raw;
        int w = (nnodes >= 8) ? ((nnodes & ~1) - 6) : 0;
        bool is64 = (b32[w + 1] == 0) && (b32[w + 3] == 0) && (b32[w + 5] == 0);
        const long long* b64 = (const long long*)batch_raw;
        long long gv = (long long)(g + wid);
        int lo = 0, hi = nnodes;
        while (hi - lo > 32) {
            long long span = (long long)(hi - lo);
            int p = lo + (int)((span * (long long)(lane + 1)) >> 5);
            bool lt = (p < hi) && ((is64 ? b64[p] : (long long)b32[p]) < gv);
            unsigned m = __ballot_sync(0xffffffffu, lt);
            int c = __popc(m);
            int pc1 = __shfl_sync(0xffffffffu, p, (c > 0) ? (c - 1) : 0);
            int pc  = __shfl_sync(0xffffffffu, p, (c < 32) ? c : 31);
            if (c > 0)  lo = pc1 + 1;
            if (c < 32) hi = pc;
        }
        int p = lo + lane;
        bool ge = (p >= hi) || ((is64 ? b64[p] : (long long)b32[p]) >= gv);
        unsigned m = __ballot_sync(0xffffffffu, ge);
        int res = (m == 0u) ? hi : (lo + (__ffs(m) - 1));
        if (lane == 0) bounds[wid] = res;
    }
    __syncthreads();
    int n0 = bounds[0], n1 = bounds[1];

    // ---- phase A: 2 nodes per 8-lane group per iter; loads front-batched ----
    float acc = 0.f;
    for (int base = n0; base < n1; base += NPB) {
        int nd0 = base + wid * 8 + grp * 2;
        int nd1 = nd0 + 1;
        bool v0 = nd0 < n1, v1 = nd1 < n1;
        float4 va[4], vb[4];
        const float* ra = ns + (long)nd0 * NDIM + l8 * 4;
        const float* rb = ns + (long)nd1 * NDIM + l8 * 4;
        #pragma unroll
        for (int jc = 0; jc < 4; jc++)
            va[jc] = v0 ? *reinterpret_cast<const float4*>(ra + jc * 32)
                        : make_float4(0.f, 0.f, 0.f, 0.f);
        #pragma unroll
        for (int jc = 0; jc < 4; jc++)
            vb[jc] = v1 ? *reinterpret_cast<const float4*>(rb + jc * 32)
                        : make_float4(0.f, 0.f, 0.f, 0.f);
        float s0 = 0.f, s1 = 0.f;
        #pragma unroll
        for (int jc = 0; jc < 4; jc++) {
            s0 += va[jc].x * Mc[jc].x + va[jc].y * Mc[jc].y
                + va[jc].z * Mc[jc].z + va[jc].w * Mc[jc].w;
            s1 += vb[jc].x * Mc[jc].x + vb[jc].y * Mc[jc].y
                + vb[jc].z * Mc[jc].z + vb[jc].w * Mc[jc].w;
        }
        s0 += __shfl_xor_sync(0xffffffffu, s0, 1);
        s1 += __shfl_xor_sync(0xffffffffu, s1, 1);
        s0 += __shfl_xor_sync(0xffffffffu, s0, 2);
        s1 += __shfl_xor_sync(0xffffffffu, s1, 2);
        s0 += __shfl_xor_sync(0xffffffffu, s0, 4);
        s1 += __shfl_xor_sync(0xffffffffu, s1, 4);
        if (l8 == 0) {
            if (v0) {
                float a0 = softplus_fast((s0 + cg) * ATT_SCALE);
                acc += a0;
                int li = nd0 - n0;
                if (li < CAP) sm_attn[li] = a0;
            }
            if (v1) {
                float a1 = softplus_fast((s1 + cg) * ATT_SCALE);
                acc += a1;
                int li = nd1 - n0;
                if (li < CAP) sm_attn[li] = a1;
            }
        }
    }
    #pragma unroll
    for (int o = 16; o > 0; o >>= 1) acc += __shfl_xor_sync(0xffffffffu, acc, o);
    if (lane == 0) warpsum[wid] = acc;
    __syncthreads();
    float asum = warpsum[0] + warpsum[1] + warpsum[2] + warpsum[3];
    float inv = 1.0f / asum;

    // ---- wait for aux grid completion (psi needed only from here) ----
    cudaGridDependencySynchronize();

    // ---- phase B: table epilogue; evict-first reads, streaming stores ----
    for (int base = n0; base < n1; base += NPB_B) {
        int node = base + wid * 4 + grp;
        if (node >= n1) continue;
        int li = node - n0;
        float attn;
        if (li < CAP) {
            attn = sm_attn[li];
        } else {
            float s = 0.f;
            const float* row = ns + (long)node * NDIM + l8 * 4;
            #pragma unroll
            for (int jc = 0; jc < 4; jc++) {
                float4 v = __ldcs(reinterpret_cast<const float4*>(row + jc * 32));
                s += v.x * Mc[jc].x + v.y * Mc[jc].y + v.z * Mc[jc].z + v.w * Mc[jc].w;
            }
            s += __shfl_xor_sync(0xffffffffu, s, 1);
            s += __shfl_xor_sync(0xffffffffu, s, 2);
            s += __shfl_xor_sync(0xffffffffu, s, 4);
            attn = softplus_fast((s + cg) * ATT_SCALE);
        }
        float beta = attn * inv * qb;
        float tf = (float)TABK * sqrtf(beta * INV_BMAX);
        int idx = (int)tf;
        if (idx > TABK - 1) idx = TABK - 1;
        float f = tf - (float)idx;
        const float* pa = &g_psi[jj][idx][0];
        const float* row = ns + (long)node * NDIM;
        float* orow = out + (long)node * NDIM;
        #pragma unroll
        for (int jc = 0; jc < 4; jc++) {
            int e = jc * 32 + l8 * 4;
            float4 v = __ldcs(reinterpret_cast<const float4*>(row + e));
            float4 a = *reinterpret_cast<const float4*>(pa + e);
            float4 b = *reinterpret_cast<const float4*>(pa + NDIM + e);
            float4 o4;
            o4.x = v.x + fmaf(f, b.x - a.x, a.x);
            o4.y = v.y + fmaf(f, b.y - a.y, a.y);
            o4.z = v.z + fmaf(f, b.z - a.z, a.z);
            o4.w = v.w + fmaf(f, b.w - a.w, a.w);
            __stcs(reinterpret_cast<float4*>(orow + e), o4);
        }
    }
}

extern "C" void kernel_launch(void* const* d_in, const int* in_sizes, int n_in,
                              void* d_out, int out_size) {
    const float* ns     = (const float*)d_in[0];
    const float* charge = (const float*)d_in[1];
    const void*  batch  = (const void*) d_in[2];
    const float* Wq     = (const float*)d_in[3];
    const float* bq     = (const float*)d_in[4];
    const float* Wk     = (const float*)d_in[5];
    const float* Wv     = (const float*)d_in[6];
    const float* W1     = (const float*)d_in[7];
    const float* b1     = (const float*)d_in[8];
    const float* W2     = (const float*)d_in[9];
    const float* b2     = (const float*)d_in[10];
    float* out = (float*)d_out;

    int nnodes  = in_sizes[0] / NDIM;
    int ngraphs = in_sizes[1];

    // aux: M/Kb (pre-trigger) + psi table (post-trigger)
    aux_kernel<<<1 + NTAB2, 128>>>(Wq, bq, Wk, Wv, W1, b1, W2, b2);

    // main: PDL secondary — own-bounds search + phase A overlap the table
    cudaLaunchConfig_t cfg = {};
    cfg.gridDim  = dim3((unsigned)ngraphs, 1, 1);
    cfg.blockDim = dim3(128, 1, 1);
    cfg.dynamicSmemBytes = 0;
    cfg.stream = 0;
    cudaLaunchAttribute attrs[1];
    attrs[0].id = cudaLaunchAttributeProgrammaticStreamSerialization;
    attrs[0].val.programmaticStreamSerializationAllowed = 1;
    cfg.attrs = attrs;
    cfg.numAttrs = 1;
    cudaLaunchKernelEx(&cfg, main_kernel, ns, charge, batch, nnodes, ngraphs, out);
}